// round 17
// baseline (speedup 1.0000x reference)
#include <cuda_runtime.h>
#include <cuda_bf16.h>
#include <cstdint>

#define GCN_D     64
#define GCN_C     40
#define GCN_NMAX  100000
#define GCN_EMAX  800000
#define SCAN_T    1024

typedef unsigned long long u64;

// Scratch (device globals: no allocation allowed in kernel_launch)
__device__ float g_dinv[GCN_NMAX];
__device__ float g_tmp[(size_t)GCN_NMAX * GCN_D];   // h @ W
__device__ float g_h[(size_t)GCN_NMAX * GCN_D];     // aggregated output
__device__ uint2 g_wh[3 * 1024];                    // W0/W1/W2 bf16 hi (pre-split)
__device__ uint2 g_wl[3 * 1024];                    // W0/W1/W2 bf16 lo
__device__ int   g_cnt[GCN_NMAX];
__device__ int   g_off[GCN_NMAX];
__device__ int2  g_offcnt[GCN_NMAX];                // {block-local off, cnt}
__device__ int   g_cur[GCN_NMAX];
__device__ int   g_bsum[256];
__device__ u64   g_epack[GCN_EMAX];                 // packed {src, norm}
// degree-balanced ordering
__device__ int   g_dcnt[64];
__device__ int   g_doff[64];
__device__ int   g_dcur[64];
__device__ int   g_order[GCN_NMAX];

// Streams/events (host-side ctor; no device alloc)
struct GcnRes {
    cudaStream_t s1, s2;
    cudaEvent_t e0, e1, e2, e3, e4;
    GcnRes() {
        cudaStreamCreateWithFlags(&s1, cudaStreamNonBlocking);
        cudaStreamCreateWithFlags(&s2, cudaStreamNonBlocking);
        cudaEventCreateWithFlags(&e0, cudaEventDisableTiming);
        cudaEventCreateWithFlags(&e1, cudaEventDisableTiming);
        cudaEventCreateWithFlags(&e2, cudaEventDisableTiming);
        cudaEventCreateWithFlags(&e3, cudaEventDisableTiming);
        cudaEventCreateWithFlags(&e4, cudaEventDisableTiming);
    }
};
static GcnRes g_res;

// ---------------------------------------------------------------------------
// Packed fp32x2 + bf16 helpers
// ---------------------------------------------------------------------------
__device__ __forceinline__ u64 ffma2(u64 a, u64 b, u64 c) {
    u64 d;
    asm("fma.rn.f32x2 %0, %1, %2, %3;" : "=l"(d) : "l"(a), "l"(b), "l"(c));
    return d;
}
__device__ __forceinline__ u64 mul2(u64 a, u64 b) {
    u64 d;
    asm("mul.rn.f32x2 %0, %1, %2;" : "=l"(d) : "l"(a), "l"(b));
    return d;
}
__device__ __forceinline__ u64 pack2(float v) {
    u64 r;
    asm("mov.b64 %0, {%1, %1};" : "=l"(r) : "f"(v));
    return r;
}
__device__ __forceinline__ uint32_t cvt_bf16x2(float lo, float hi) {
    uint32_t r;
    asm("cvt.rn.satfinite.bf16x2.f32 %0, %1, %2;" : "=r"(r) : "f"(hi), "f"(lo));
    return r;
}
__device__ __forceinline__ void split4(const float* xs, uint2& hv, uint2& lv) {
    hv.x = cvt_bf16x2(xs[0], xs[1]);
    hv.y = cvt_bf16x2(xs[2], xs[3]);
    float h0 = __uint_as_float(hv.x << 16);
    float h1 = __uint_as_float(hv.x & 0xFFFF0000u);
    float h2 = __uint_as_float(hv.y << 16);
    float h3 = __uint_as_float(hv.y & 0xFFFF0000u);
    lv.x = cvt_bf16x2(xs[0] - h0, xs[1] - h1);
    lv.y = cvt_bf16x2(xs[2] - h2, xs[3] - h3);
}

// ---------------------------------------------------------------------------
// HMMA helpers (mma.sync bf16, sm_80+)
// ---------------------------------------------------------------------------
__device__ __forceinline__ uint32_t smem_u32(const void* p) {
    uint32_t a;
    asm("{ .reg .u64 t; cvta.to.shared.u64 t, %1; cvt.u32.u64 %0, t; }"
        : "=r"(a) : "l"(p));
    return a;
}
__device__ __forceinline__ void ldm_x4_t(uint32_t& r0, uint32_t& r1,
                                         uint32_t& r2, uint32_t& r3,
                                         uint32_t addr) {
    asm volatile("ldmatrix.sync.aligned.m8n8.x4.trans.shared.b16 {%0,%1,%2,%3}, [%4];"
                 : "=r"(r0), "=r"(r1), "=r"(r2), "=r"(r3) : "r"(addr));
}
__device__ __forceinline__ void mma_bf16(float* d, const uint32_t* a,
                                         uint32_t b0, uint32_t b1) {
    asm volatile(
        "mma.sync.aligned.m16n8k16.row.col.f32.bf16.bf16.f32 "
        "{%0,%1,%2,%3}, {%4,%5,%6,%7}, {%8,%9}, {%0,%1,%2,%3};"
        : "+f"(d[0]), "+f"(d[1]), "+f"(d[2]), "+f"(d[3])
        : "r"(a[0]), "r"(a[1]), "r"(a[2]), "r"(a[3]), "r"(b0), "r"(b1));
}

// ---------------------------------------------------------------------------
// CSR build + degree sort
// ---------------------------------------------------------------------------
__global__ void k_count(const int* __restrict__ dst, int E) {
    int e = blockIdx.x * blockDim.x + threadIdx.x;
    if (e < E) atomicAdd(&g_cnt[dst[e]], 1);
}

__global__ void k_scan1(int N) {
    __shared__ int sh[SCAN_T];
    __shared__ int hist[64];
    int t = threadIdx.x;
    if (t < 64) hist[t] = 0;
    int idx = blockIdx.x * SCAN_T + t;
    int v = (idx < N) ? g_cnt[idx] : 0;
    sh[t] = v;
    __syncthreads();
    for (int o = 1; o < SCAN_T; o <<= 1) {
        int a = (t >= o) ? sh[t - o] : 0;
        __syncthreads();
        sh[t] += a;
        __syncthreads();
    }
    if (idx < N) {
        int off = sh[t] - v;
        g_off[idx] = off;
        g_offcnt[idx] = make_int2(off, v);
        g_cur[idx] = 0;
        g_dinv[idx] = rsqrtf((float)(v + 1));
        atomicAdd(&hist[min(v, 63)], 1);
    }
    if (t == SCAN_T - 1) g_bsum[blockIdx.x] = sh[t];
    __syncthreads();
    if (t < 64 && hist[t]) atomicAdd(&g_dcnt[t], hist[t]);
}

__global__ void k_scan2(int nb) {
    __shared__ int sh[256];
    int t = threadIdx.x;
    int v = (t < nb) ? g_bsum[t] : 0;
    sh[t] = v;
    __syncthreads();
    for (int o = 1; o < 256; o <<= 1) {
        int a = (t >= o) ? sh[t - o] : 0;
        __syncthreads();
        sh[t] += a;
        __syncthreads();
    }
    if (t < nb) g_bsum[t] = sh[t] - v;
    __syncthreads();
    int v2 = (t < 64) ? g_dcnt[t] : 0;
    sh[t] = v2;
    __syncthreads();
    for (int o = 1; o < 64; o <<= 1) {
        int a = (t >= o && t < 64) ? sh[t - o] : 0;
        __syncthreads();
        if (t < 64) sh[t] += a;
        __syncthreads();
    }
    if (t < 64) {
        g_doff[t] = sh[t] - v2;
        g_dcur[t] = 0;
    }
}

__global__ void k_dfill(int N) {
    __shared__ int hist[64], base[64];
    int t = threadIdx.x;
    if (t < 64) hist[t] = 0;
    __syncthreads();
    int i = blockIdx.x * blockDim.x + t;
    int d = 0, local = 0;
    if (i < N) {
        d = min(g_cnt[i], 63);
        local = atomicAdd(&hist[d], 1);
    }
    __syncthreads();
    if (t < 64 && hist[t]) base[t] = atomicAdd(&g_dcur[t], hist[t]);
    __syncthreads();
    if (i < N) g_order[g_doff[d] + base[d] + local] = i;
}

__global__ void k_fill(const int* __restrict__ src, const int* __restrict__ dst,
                       int E) {
    int e = blockIdx.x * blockDim.x + threadIdx.x;
    if (e >= E) return;
    int d = dst[e];
    int s = src[e];
    int pos = g_off[d] + g_bsum[d >> 10] + atomicAdd(&g_cur[d], 1);
    float nrm = g_dinv[s] * g_dinv[d];
    g_epack[pos] = (u64)(unsigned)s | ((u64)__float_as_uint(nrm) << 32);
}

__global__ void k_convw(const float* __restrict__ W0,
                        const float* __restrict__ W1,
                        const float* __restrict__ W2) {
    int i = blockIdx.x * blockDim.x + threadIdx.x;   // 0..3071
    if (i >= 3072) return;
    const float* W = (i < 1024) ? W0 : (i < 2048) ? W1 : W2;
    float4 v = ((const float4*)W)[i & 1023];
    const float xs[4] = {v.x, v.y, v.z, v.w};
    uint2 hv, lv;
    split4(xs, hv, lv);
    g_wh[i] = hv;
    g_wl[i] = lv;
}

// ---------------------------------------------------------------------------
// Register-direct tensor-core GEMM (R16 proven).
// ---------------------------------------------------------------------------
#define GS 72

__global__ __launch_bounds__(256) void k_gemm_hmma(const float* __restrict__ Xext,
                                                   int N, int use_h, int layer) {
    __shared__ __align__(16) unsigned short Bhi[64 * GS];
    __shared__ __align__(16) unsigned short Blo[64 * GS];

    const float* __restrict__ X = use_h ? g_h : Xext;
    int tid = threadIdx.x;
    int rowbase = blockIdx.x * 128;

    {
        const uint2* __restrict__ wh = g_wh + layer * 1024;
        const uint2* __restrict__ wl = g_wl + layer * 1024;
        for (int i = tid; i < 1024; i += 256) {
            int e = (i >> 4) * GS + (i & 15) * 4;
            *(uint2*)&Bhi[e] = wh[i];
            *(uint2*)&Blo[e] = wl[i];
        }
    }
    __syncthreads();

    int w = tid >> 5;
    int lane = tid & 31;
    int r0 = rowbase + w * 16 + (lane >> 2);
    int r1 = r0 + 8;
    bool v0 = r0 < N, v1 = r1 < N;
    int cbase = (lane & 3) * 2;
    const float2* __restrict__ X2 = (const float2*)X;
    size_t ro0 = (size_t)r0 * 32;
    size_t ro1 = (size_t)r1 * 32;

    float2 f[4][4];
#pragma unroll
    for (int kc = 0; kc < 4; kc++) {
        int c0 = (kc * 16 + cbase) >> 1;
        f[kc][0] = v0 ? X2[ro0 + c0]     : make_float2(0.f, 0.f);
        f[kc][1] = v1 ? X2[ro1 + c0]     : make_float2(0.f, 0.f);
        f[kc][2] = v0 ? X2[ro0 + c0 + 4] : make_float2(0.f, 0.f);
        f[kc][3] = v1 ? X2[ro1 + c0 + 4] : make_float2(0.f, 0.f);
    }

    float acc[8][4];
#pragma unroll
    for (int j = 0; j < 8; j++)
#pragma unroll
        for (int q = 0; q < 4; q++) acc[j][q] = 0.f;

    uint32_t bhi_base = smem_u32(Bhi);
    uint32_t blo_base = smem_u32(Blo);
    uint32_t b_row = (uint32_t)((lane & 7) + 8 * ((lane >> 3) & 1));
    uint32_t b_colh = (uint32_t)((lane >> 4) * 16);

#pragma unroll
    for (int kc = 0; kc < 4; kc++) {
        uint32_t ah[4], al[4];
#pragma unroll
        for (int q = 0; q < 4; q++) {
            float x0 = f[kc][q].x, x1 = f[kc][q].y;
            ah[q] = cvt_bf16x2(x0, x1);
            float h0 = __uint_as_float(ah[q] << 16);
            float h1 = __uint_as_float(ah[q] & 0xFFFF0000u);
            al[q] = cvt_bf16x2(x0 - h0, x1 - h1);
        }
        uint32_t b_off = (uint32_t)(kc * 16 + b_row) * GS * 2 + b_colh;
#pragma unroll
        for (int p = 0; p < 4; p++) {
            uint32_t bh0, bh1, bh2, bh3, bl0, bl1, bl2, bl3;
            ldm_x4_t(bh0, bh1, bh2, bh3, bhi_base + b_off + p * 32);
            ldm_x4_t(bl0, bl1, bl2, bl3, blo_base + b_off + p * 32);
            mma_bf16(acc[2 * p + 0], ah, bh0, bh1);
            mma_bf16(acc[2 * p + 1], ah, bh2, bh3);
            mma_bf16(acc[2 * p + 0], ah, bl0, bl1);
            mma_bf16(acc[2 * p + 1], ah, bl2, bl3);
            mma_bf16(acc[2 * p + 0], al, bh0, bh1);
            mma_bf16(acc[2 * p + 1], al, bh2, bh3);
        }
    }

#pragma unroll
    for (int j = 0; j < 8; j++) {
        if (v0)
            *(float2*)&g_tmp[(size_t)r0 * 64 + 8 * j + cbase] =
                make_float2(acc[j][0], acc[j][1]);
        if (v1)
            *(float2*)&g_tmp[(size_t)r1 * 64 + 8 * j + cbase] =
                make_float2(acc[j][2], acc[j][3]);
    }
}

// ---------------------------------------------------------------------------
// Fused aggregation (R8 geometry) over degree-sorted node order.
// off/cnt fetched as one LDG.64.
// ---------------------------------------------------------------------------
__global__ __launch_bounds__(256) void k_agg(const float* __restrict__ b, int N) {
    int t = blockIdx.x * blockDim.x + threadIdx.x;
    int gidx = t >> 4;
    if (gidx >= N) return;
    int node = g_order[gidx];
    int l = t & 15;

    const ulonglong2* __restrict__ tmp4 = (const ulonglong2*)g_tmp;
    float di = g_dinv[node];
    ulonglong2 self = tmp4[(size_t)node * 16 + l];
    u64 s2 = pack2(di * di);
    ulonglong2 acc;
    acc.x = mul2(self.x, s2);
    acc.y = mul2(self.y, s2);

    int2 oc = g_offcnt[node];
    int off = oc.x + g_bsum[node >> 10];
    int cnt = oc.y;
    const u64* __restrict__ ep = g_epack + off;

    int j = 0;
    for (; j + 8 <= cnt; j += 8) {
        u64 p[8];
#pragma unroll
        for (int q = 0; q < 8; q++) p[q] = ep[j + q];
        ulonglong2 v[8];
#pragma unroll
        for (int q = 0; q < 8; q++)
            v[q] = tmp4[(size_t)(unsigned)p[q] * 16 + l];
#pragma unroll
        for (int q = 0; q < 8; q++) {
            u64 nn = pack2(__uint_as_float((unsigned)(p[q] >> 32)));
            acc.x = ffma2(v[q].x, nn, acc.x);
            acc.y = ffma2(v[q].y, nn, acc.y);
        }
    }
    for (; j < cnt; j++) {
        u64 p = ep[j];
        u64 nn = pack2(__uint_as_float((unsigned)(p >> 32)));
        ulonglong2 v = tmp4[(size_t)(unsigned)p * 16 + l];
        acc.x = ffma2(v.x, nn, acc.x);
        acc.y = ffma2(v.y, nn, acc.y);
    }

    float4 bv = ((const float4*)b)[l];
    float2 lo = *(float2*)&acc.x;
    float2 hi = *(float2*)&acc.y;
    float4 r;
    r.x = fmaxf(lo.x + bv.x, 0.f);
    r.y = fmaxf(lo.y + bv.y, 0.f);
    r.z = fmaxf(hi.x + bv.z, 0.f);
    r.w = fmaxf(hi.y + bv.w, 0.f);
    ((float4*)g_h)[(size_t)node * 16 + l] = r;
}

// ---------------------------------------------------------------------------
// Classifier + log_softmax (packed fp32x2)
// ---------------------------------------------------------------------------
__global__ __launch_bounds__(128) void k_classify(const float* __restrict__ Wc,
                                                  const float* __restrict__ bc,
                                                  float* __restrict__ out, int N) {
    __shared__ ulonglong2 Ws[GCN_D * 10];
    __shared__ float bs[GCN_C];
    for (int i = threadIdx.x; i < GCN_D * 10; i += blockDim.x)
        Ws[i] = ((const ulonglong2*)Wc)[i];
    for (int i = threadIdx.x; i < GCN_C; i += blockDim.x)
        bs[i] = bc[i];
    __syncthreads();

    int n = blockIdx.x * blockDim.x + threadIdx.x;
    if (n >= N) return;

    u64 acc[20];
    {
        const u64* bp = (const u64*)bs;
#pragma unroll
        for (int c = 0; c < 20; c++) acc[c] = bp[c];
    }

    const float4* hr = (const float4*)(g_h + (size_t)n * GCN_D);
#pragma unroll 4
    for (int k4 = 0; k4 < 16; k4++) {
        float4 xv = hr[k4];
        const float xs[4] = {xv.x, xv.y, xv.z, xv.w};
#pragma unroll
        for (int kk = 0; kk < 4; kk++) {
            u64 xx = pack2(xs[kk]);
            int k = 4 * k4 + kk;
#pragma unroll
            for (int c = 0; c < 10; c++) {
                ulonglong2 w = Ws[k * 10 + c];
                acc[2 * c + 0] = ffma2(xx, w.x, acc[2 * c + 0]);
                acc[2 * c + 1] = ffma2(xx, w.y, acc[2 * c + 1]);
            }
        }
    }

    float a[GCN_C];
#pragma unroll
    for (int c = 0; c < 20; c++) {
        a[2 * c]     = __uint_as_float((unsigned)(acc[c] & 0xffffffffu));
        a[2 * c + 1] = __uint_as_float((unsigned)(acc[c] >> 32));
    }
    float m = a[0];
#pragma unroll
    for (int c = 1; c < GCN_C; c++) m = fmaxf(m, a[c]);
    float sum = 0.f;
#pragma unroll
    for (int c = 0; c < GCN_C; c++) sum += expf(a[c] - m);
    float lse = logf(sum) + m;
    float* op = out + (size_t)n * GCN_C;
#pragma unroll
    for (int c = 0; c < GCN_C; c++) op[c] = a[c] - lse;
}

// ---------------------------------------------------------------------------
// Launch — main (GEMM/agg chain), s1 (convw, then dfill), s2 (CSR chain);
// dfill runs concurrently with fill.
// ---------------------------------------------------------------------------
extern "C" void kernel_launch(void* const* d_in, const int* in_sizes, int n_in,
                              void* d_out, int out_size) {
    const float* x  = (const float*)d_in[0];
    const int*   ei = (const int*)d_in[1];
    const float* W0 = (const float*)d_in[2];
    const float* b0 = (const float*)d_in[3];
    const float* W1 = (const float*)d_in[4];
    const float* b1 = (const float*)d_in[5];
    const float* W2 = (const float*)d_in[6];
    const float* b2 = (const float*)d_in[7];
    const float* Wc = (const float*)d_in[8];
    const float* bc = (const float*)d_in[9];
    float* out = (float*)d_out;

    int N = in_sizes[0] / GCN_D;
    int E = in_sizes[1] / 2;
    const int* src = ei;
    const int* dst = ei + E;

    int nb_n  = (N + 255) / 256;
    int nb_e  = (E + 255) / 256;
    int nb_g  = (N + 127) / 128;
    int nb_s  = (N + SCAN_T - 1) / SCAN_T;
    int nb_a  = (int)(((long long)N * 16 + 255) / 256);

    cudaStream_t s1 = g_res.s1;
    cudaStream_t s2 = g_res.s2;

    void *p_cnt, *p_dcnt;
    cudaGetSymbolAddress(&p_cnt, g_cnt);
    cudaGetSymbolAddress(&p_dcnt, g_dcnt);

    // Fork.
    cudaEventRecord(g_res.e0, 0);
    cudaStreamWaitEvent(s1, g_res.e0, 0);
    cudaStreamWaitEvent(s2, g_res.e0, 0);

    // s1: W pre-split (gemm0's sole dependency)
    k_convw<<<12, 256, 0, s1>>>(W0, W1, W2);
    cudaEventRecord(g_res.e2, s1);

    // s2: CSR chain
    cudaMemsetAsync(p_cnt, 0, (size_t)N * sizeof(int), s2);
    cudaMemsetAsync(p_dcnt, 0, 64 * sizeof(int), s2);
    k_count<<<nb_e, 256, 0, s2>>>(dst, E);
    k_scan1<<<nb_s, SCAN_T, 0, s2>>>(N);
    k_scan2<<<1, 256, 0, s2>>>(nb_s);
    cudaEventRecord(g_res.e3, s2);              // scan2 done
    k_fill<<<nb_e, 256, 0, s2>>>(src, dst, E);
    cudaEventRecord(g_res.e1, s2);

    // s1 (after convw): dfill concurrent with fill
    cudaStreamWaitEvent(s1, g_res.e3, 0);
    k_dfill<<<nb_n, 256, 0, s1>>>(N);
    cudaEventRecord(g_res.e4, s1);

    // main: gemm0 (waits convw), then join CSR + dfill, then the layer chain
    cudaStreamWaitEvent(0, g_res.e2, 0);
    k_gemm_hmma<<<nb_g, 256>>>(x, N, 0, 0);
    cudaStreamWaitEvent(0, g_res.e1, 0);
    cudaStreamWaitEvent(0, g_res.e4, 0);

    k_agg<<<nb_a, 256>>>(b0, N);
    k_gemm_hmma<<<nb_g, 256>>>(x, N, 1, 1);
    k_agg<<<nb_a, 256>>>(b1, N);
    k_gemm_hmma<<<nb_g, 256>>>(x, N, 1, 2);
    k_agg<<<nb_a, 256>>>(b2, N);

    k_classify<<<(N + 127) / 128, 128>>>(Wc, bc, out, N);
}